// round 16
// baseline (speedup 1.0000x reference)
#include <cuda_runtime.h>
#include <cuda_fp16.h>
#include <cstdint>

// Problem constants
#define Hn    128
#define Ln    512
#define Bn    128
#define VOCABn 32000
#define NPTn  1023                 // 2L-1 nodes per tree
#define NTOT  (Bn * NPTn)          // 130944 nodes
#define NLEAF (Bn * Ln)            // 65536 leaves

// Persistent device state (no allocation allowed)
__device__ float g_h[NTOT * Hn];                       // fp32 h (only roots written; final proj)
__device__ float g_c[NTOT * Hn];                       // fp32 c chain
__device__ __half g_hf[NTOT * Hn];                     // f16 h mirror (GEMM operand)
__device__ __half g_embH[VOCABn * Hn];                 // f16 emb
__device__ __half g_WTh[640 * 256];                    // permuted [Ufw|Uiou]^T, f16, [c][k], c=d*5+g
__device__ __half g_WioTh[384 * 128];                  // permuted W_iou^T, f16, [c][k], c=d*3+g

// HW tanh (single MUFU op, sm_75+); sigmoid via tanh identity.
__device__ __forceinline__ float tanh_ap(float x) {
    float r; asm("tanh.approx.f32 %0, %1;" : "=f"(r) : "f"(x)); return r;
}
__device__ __forceinline__ float sigm_ap(float x) {
    return fmaf(0.5f, tanh_ap(0.5f * x), 0.5f);
}

// m16n8k16 f16 MMA, f16 accum (2-reg D fragment; legacy HMMA, plain compute_103)
__device__ __forceinline__ void mma_f16(uint32_t& d0, uint32_t& d1,
                                        uint32_t a0, uint32_t a1, uint32_t a2, uint32_t a3,
                                        uint32_t b0, uint32_t b1) {
    asm volatile(
        "mma.sync.aligned.m16n8k16.row.col.f16.f16.f16.f16 "
        "{%0,%1}, {%2,%3,%4,%5}, {%6,%7}, {%0,%1};"
        : "+r"(d0), "+r"(d1)
        : "r"(a0), "r"(a1), "r"(a2), "r"(a3), "r"(b0), "r"(b1));
}

__device__ __forceinline__ void ldsm4(uint32_t& r0, uint32_t& r1, uint32_t& r2, uint32_t& r3,
                                      uint32_t addr) {
    asm volatile("ldmatrix.sync.aligned.m8n8.x4.shared.b16 {%0,%1,%2,%3}, [%4];"
                 : "=r"(r0), "=r"(r1), "=r"(r2), "=r"(r3) : "r"(addr));
}
__device__ __forceinline__ void ldsm2(uint32_t& r0, uint32_t& r1, uint32_t addr) {
    asm volatile("ldmatrix.sync.aligned.m8n8.x2.shared.b16 {%0,%1}, [%2];"
                 : "=r"(r0), "=r"(r1) : "r"(addr));
}

__device__ __forceinline__ uint32_t smem_u32(const void* p) {
    uint32_t a;
    asm("{ .reg .u64 t; cvta.to.shared.u64 t, %1; cvt.u32.u64 %0, t; }" : "=r"(a) : "l"(p));
    return a;
}
__device__ __forceinline__ void cpa16(uint32_t s, const void* g) {
    asm volatile("cp.async.cg.shared.global [%0], [%1], 16;" :: "r"(s), "l"(g));
}
#define CP_COMMIT() asm volatile("cp.async.commit_group;" ::: "memory")
#define CP_WAIT(N)  asm volatile("cp.async.wait_group %0;" :: "n"(N) : "memory")

// ---------------------------------------------------------------------------
// Prep kernels: weight transpose to gate-interleaved K-major f16; emb -> f16.
// Level: c = d*5 + g (g0=Ufw[:,d], g1=Ufw[:,128+d], g2..4=Uiou[:,{0,128,256}+d])
// Leaf:  c = d*3 + g (g=Wiou[:, g*128+d])
// ---------------------------------------------------------------------------
__global__ __launch_bounds__(256) void prep_WT(const float* __restrict__ Ufw,
                                               const float* __restrict__ Uiou) {
    int idx = blockIdx.x * 256 + threadIdx.x;
    if (idx >= 640 * 256) return;
    int c = idx >> 8, k = idx & 255;
    int d = c / 5, g = c % 5;
    float v;
    if (g == 0)      v = Ufw[k * 256 + d];
    else if (g == 1) v = Ufw[k * 256 + 128 + d];
    else             v = Uiou[k * 384 + (g - 2) * 128 + d];
    g_WTh[idx] = __float2half(v);
}
__global__ __launch_bounds__(256) void prep_WioT(const float* __restrict__ Wiou) {
    int idx = blockIdx.x * 256 + threadIdx.x;
    if (idx >= 384 * 128) return;
    int c = idx >> 7, k = idx & 127;
    int d = c / 3, g = c % 3;
    g_WioTh[idx] = __float2half(Wiou[k * 384 + g * 128 + d]);
}
__global__ __launch_bounds__(256) void prep_emb(const float* __restrict__ emb) {
    int idx = blockIdx.x * 256 + threadIdx.x;           // VOCABn*Hn/2
    float2 v = *(const float2*)(emb + idx * 2);
    __half2 t = __floats2half2_rn(v.x, v.y);
    *(__half2*)(g_embH + idx * 2) = t;
}

// ---------------------------------------------------------------------------
// Fused f16-MMA GEMM + LSTM-cell-apply. cp.async staging (double-buffered when
// K has >1 chunk), ldmatrix fragments, f16 accumulators (u32-packed pairs).
// Epilogue: packed acc -> SMEM out (u32 stride OSTU, odd), apply unpacks
// gates, writes g_c (fp32) / g_hf (f16) [+ g_h fp32 at root level].
// LEAF:  A = g_embH[label[node]], K=128 in ONE chunk, NCOLS=96 (32 d x 3)
// LEVEL: A = 256 f16 of g_hf at child base, K=256 in 4x64 chunks, NCOLS=80 (16 d x 5)
// ---------------------------------------------------------------------------
template <int CM, int NCOLS, int KTOT, int KCH, int GATES, int OSTU, int MINB, bool LEAF>
__global__ __launch_bounds__(256, MINB)
void fused_gemm(const int* __restrict__ label,
                const float* __restrict__ b_iou, const float* __restrict__ Ufb,
                int shift, int off, int choff) {
    const int MTT  = CM / 64;            // m16 tiles per warp (4 M-warps)
    const int NTT  = NCOLS / 16;         // n8 tiles per warp  (2 N-warps)
    const int DN   = NCOLS / GATES;      // d's per CTA (32 leaf, 16 level)
    const int LOGD = (DN == 32) ? 5 : 4;
    const int NCH  = KTOT / KCH;         // K chunks (leaf 1, level 4)
    const int SABY = KCH * 2 + 16;       // bytes per staged row (pad keeps 4r-bank pattern)
    const int QA   = KCH / 8;            // 16B transfers per row
    const int BUFB = (CM + NCOLS) * SABY;

    extern __shared__ float dyn[];       // stage buffers; out aliases from 0
    char*     dynb = (char*)dyn;
    uint32_t* out  = (uint32_t*)dyn;     // CM x OSTU packed half2
    __shared__ int abase[CM];

    const __half* Ab = LEAF ? g_embH : g_hf;
    const __half* BT = LEAF ? g_WioTh : g_WTh;

    int tid  = threadIdx.x;
    int wid  = tid >> 5, lane = tid & 31;
    int grp  = lane >> 2, qid = lane & 3;
    int row0 = blockIdx.x * CM;
    int col0 = blockIdx.y * NCOLS;
    int wm0  = (wid >> 1) * (CM / 4);
    int wn0  = (wid & 1) * (NCOLS / 2);

    if (tid < CM) {
        int r = row0 + tid;
        int base;
        if (LEAF) {
            int g = (r >> 9) * NPTn + (r & 511);
            base = label[g] * Hn;
        } else {
            int t = r >> shift, j = r & ((1 << shift) - 1);
            base = (t * NPTn + choff + 2 * j) * Hn;
        }
        abase[tid] = base;
    }
    __syncthreads();

    uint32_t sbase = smem_u32(dynb);

    // Per-thread ldmatrix base addresses (buffer 0, chunk 0).
    int arow = (lane & 7) + ((lane >> 3) & 1) * 8;
    uint32_t aaddr0 = sbase + (uint32_t)(wm0 + arow) * SABY + ((lane >> 4) * 16);
    int brow = (lane & 7) + (lane >> 4) * 8;
    uint32_t baddr0 = sbase + (uint32_t)CM * SABY + (uint32_t)(wn0 + brow) * SABY
                    + (((lane >> 3) & 1) * 16);
    uint32_t baddr2 = sbase + (uint32_t)CM * SABY + (uint32_t)(wn0 + (lane & 7)) * SABY
                    + (((lane >> 3) & 1) * 16);

    auto stage = [&](int kk, int buf) {
        uint32_t sb = sbase + buf * BUFB;
#pragma unroll
        for (int e = 0; e < CM * QA / 256; e++) {
            int i = tid + e * 256;
            int m = i / QA, q = i % QA;
            cpa16(sb + m * SABY + q * 16, Ab + abase[m] + kk + q * 8);
        }
#pragma unroll
        for (int e = 0; e < (NCOLS * QA + 255) / 256; e++) {
            int i = tid + e * 256;
            if (i < NCOLS * QA) {
                int n = i / QA, q = i % QA;
                cpa16(sb + CM * SABY + n * SABY + q * 16,
                      BT + (size_t)(col0 + n) * KTOT + kk + q * 8);
            }
        }
    };

    uint32_t acc[MTT][NTT][2];
#pragma unroll
    for (int mt = 0; mt < MTT; mt++)
#pragma unroll
        for (int nt = 0; nt < NTT; nt++) { acc[mt][nt][0] = 0u; acc[mt][nt][1] = 0u; }

    stage(0, 0);
    CP_COMMIT();

    for (int ch = 0; ch < NCH; ch++) {
        if (NCH > 1 && ch + 1 < NCH) {
            stage((ch + 1) * KCH, (ch + 1) & 1);
            CP_COMMIT();
            CP_WAIT(1);
        } else {
            CP_WAIT(0);
        }
        __syncthreads();

        uint32_t bufo = (NCH > 1) ? (uint32_t)(ch & 1) * BUFB : 0u;
#pragma unroll
        for (int ks = 0; ks < KCH / 16; ks++) {
            uint32_t kb = bufo + ks * 32;            // 16 f16 = 32 B per k16 step
            uint32_t a[MTT][4];
#pragma unroll
            for (int mt = 0; mt < MTT; mt++)
                ldsm4(a[mt][0], a[mt][1], a[mt][2], a[mt][3],
                      aaddr0 + kb + mt * 16 * SABY);
            uint32_t b[NTT][2];
#pragma unroll
            for (int np = 0; np < NTT / 2; np++)
                ldsm4(b[2 * np][0], b[2 * np][1], b[2 * np + 1][0], b[2 * np + 1][1],
                      baddr0 + kb + np * 16 * SABY);
            if (NTT & 1)
                ldsm2(b[NTT - 1][0], b[NTT - 1][1],
                      baddr2 + kb + (NTT - 1) * 8 * SABY);
#pragma unroll
            for (int mt = 0; mt < MTT; mt++)
#pragma unroll
                for (int nt = 0; nt < NTT; nt++)
                    mma_f16(acc[mt][nt][0], acc[mt][nt][1],
                            a[mt][0], a[mt][1], a[mt][2], a[mt][3],
                            b[nt][0], b[nt][1]);
        }
        __syncthreads();
    }

    // acc (packed half2 pairs) -> SMEM out buffer
#pragma unroll
    for (int mt = 0; mt < MTT; mt++) {
        int r = wm0 + mt * 16 + grp;
#pragma unroll
        for (int nt = 0; nt < NTT; nt++) {
            int p = (wn0 >> 1) + nt * 4 + qid;       // col-pair index
            out[r * OSTU + p]       = acc[mt][nt][0];
            out[(r + 8) * OSTU + p] = acc[mt][nt][1];
        }
    }
    __syncthreads();

    // Apply phase: d invariant per thread -> hoist biases.
    int d      = tid & (DN - 1);
    int rbase  = tid >> LOGD;
    const int rstep = 256 >> LOGD;
    int dg = blockIdx.y * DN + d;
    int pb = (d * GATES) >> 1;               // first u32 pair holding this d's gates
    int sel = d & 1;                          // parity: gate0 sits in lo (0) or hi (1)

    float bi = b_iou[dg], bo = b_iou[128 + dg], bu = b_iou[256 + dg];
    float bfl = 0.0f, bfr = 0.0f;
    if (!LEAF) { bfl = Ufb[dg]; bfr = Ufb[128 + dg]; }

#pragma unroll 4
    for (int row = rbase; row < CM; row += rstep) {
        int R = row0 + row;
        const uint32_t* s = out + row * OSTU + pb;
        float f[6];
        float2 v0 = __half22float2(*(const __half2*)&s[0]);
        float2 v1 = __half22float2(*(const __half2*)&s[1]);
        f[0] = v0.x; f[1] = v0.y; f[2] = v1.x; f[3] = v1.y;
        if (!LEAF) {
            float2 v2 = __half22float2(*(const __half2*)&s[2]);
            f[4] = v2.x; f[5] = v2.y;
        }
        if (LEAF) {
            int node = (R >> 9) * NPTn + (R & 511);
            float cc = sigm_ap(f[sel] + bi) * tanh_ap(f[sel + 2] + bu);
            float hh = sigm_ap(f[sel + 1] + bo) * tanh_ap(cc);
            g_c[node * Hn + dg]  = cc;
            g_hf[node * Hn + dg] = __float2half(hh);
        } else {
            int t = R >> shift, j = R & ((1 << shift) - 1);
            int tb = t * NPTn;
            int node = tb + off + j;
            int left = tb + choff + 2 * j;
            float fl = sigm_ap(f[sel] + bfl);
            float fr = sigm_ap(f[sel + 1] + bfr);
            float cred = fl * g_c[left * Hn + dg] + fr * g_c[(left + 1) * Hn + dg];
            float cc = sigm_ap(f[sel + 2] + bi) * tanh_ap(f[sel + 4] + bu) + cred;
            float hh = sigm_ap(f[sel + 3] + bo) * tanh_ap(cc);
            g_c[node * Hn + dg]  = cc;
            g_hf[node * Hn + dg] = __float2half(hh);
            if (shift == 0)                     // roots: fp32 h for final proj
                g_h[node * Hn + dg] = hh;
        }
    }
}

// Root projection + log_softmax. grid 128 (trees), block 128 (out dims).
__global__ __launch_bounds__(128) void final_kernel(const float* __restrict__ W,
                                                    const float* __restrict__ b,
                                                    float* __restrict__ out) {
    __shared__ float hr[128];
    __shared__ float red[128];
    int t = blockIdx.x, o = threadIdx.x;
    hr[o] = g_h[(t * NPTn + NPTn - 1) * Hn + o];
    __syncthreads();
    float acc = b[o];
#pragma unroll 8
    for (int k = 0; k < 128; k++) acc += hr[k] * W[k * 128 + o];
    red[o] = acc;
    __syncthreads();
#pragma unroll
    for (int s = 64; s > 0; s >>= 1) {
        if (o < s) red[o] = fmaxf(red[o], red[o + s]);
        __syncthreads();
    }
    float mx = red[0];
    __syncthreads();
    red[o] = expf(acc - mx);
    __syncthreads();
#pragma unroll
    for (int s = 64; s > 0; s >>= 1) {
        if (o < s) red[o] += red[o + s];
        __syncthreads();
    }
    out[t * 128 + o] = acc - mx - logf(red[0]);
}

// ---------------------------------------------------------------------------
// Inputs (metadata order): label, emb, W_iou, U_iou, b_iou, U_f_w, U_f_b, W_out, b_out
// ---------------------------------------------------------------------------
// Dynamic smem (bytes): max(out u32, stage buffers)
// leaf: single 272B-row buffer (128+96)*272 = 60928 ; out 128*49*4 = 25088
// lv128: 2 x (128+80)*144 = 59904 ; out 128*41*4 = 20992
// lv64:  2 x (64+80)*144  = 41472 ; out 64*41*4  = 10496
#define LEAF_SMEM  ((128 + 96) * 272)
#define LV128_SMEM (2 * (128 + 80) * 144)
#define LV64_SMEM  (2 * (64 + 80) * 144)

extern "C" void kernel_launch(void* const* d_in, const int* in_sizes, int n_in,
                              void* d_out, int out_size) {
    const int*   label = (const int*)  d_in[0];
    const float* emb   = (const float*)d_in[1];
    const float* W_iou = (const float*)d_in[2];
    const float* U_iou = (const float*)d_in[3];
    const float* b_iou = (const float*)d_in[4];
    const float* U_f_w = (const float*)d_in[5];
    const float* U_f_b = (const float*)d_in[6];
    const float* W_out = (const float*)d_in[7];
    const float* b_out = (const float*)d_in[8];
    float* out = (float*)d_out;

    // Opt-in dynamic smem (> 48 KB). Host-side attribute set; capture-safe (R10/R12+).
    cudaFuncSetAttribute((const void*)fused_gemm<128, 96, 128, 128, 3, 49, 3, true>,
                         cudaFuncAttributeMaxDynamicSharedMemorySize, LEAF_SMEM);
    cudaFuncSetAttribute((const void*)fused_gemm<128, 80, 256, 64, 5, 41, 3, false>,
                         cudaFuncAttributeMaxDynamicSharedMemorySize, LV128_SMEM);
    cudaFuncSetAttribute((const void*)fused_gemm<64, 80, 256, 64, 5, 41, 3, false>,
                         cudaFuncAttributeMaxDynamicSharedMemorySize, LV64_SMEM);

    prep_WT<<<640, 256>>>(U_f_w, U_iou);
    prep_WioT<<<192, 256>>>(W_iou);
    prep_emb<<<(VOCABn * Hn / 2) / 256, 256>>>(emb);

    // Leaves: fused [65536,128]@[128,384(permuted)] + cell update, K in one chunk
    fused_gemm<128, 96, 128, 128, 3, 49, 3, true>
        <<<dim3(NLEAF / 128, 4), 256, LEAF_SMEM>>>(label, b_iou, nullptr, 0, 0, 0);

    for (int shift = 8; shift >= 0; shift--) {
        int cnt   = 1 << shift;                 // 256 .. 1
        int off   = NPTn - (2 * cnt - 1);
        int choff = NPTn - (4 * cnt - 1);
        int nd    = Bn * cnt;                   // 32768 .. 128
        if (nd >= 8192)
            fused_gemm<128, 80, 256, 64, 5, 41, 3, false>
                <<<dim3(nd / 128, 8), 256, LV128_SMEM>>>(label, b_iou, U_f_b,
                                                         shift, off, choff);
        else
            fused_gemm<64, 80, 256, 64, 5, 41, 3, false>
                <<<dim3(nd / 64, 8), 256, LV64_SMEM>>>(label, b_iou, U_f_b,
                                                       shift, off, choff);
    }

    final_kernel<<<Bn, 128>>>(W_out, b_out, out);
}

// round 17
// speedup vs baseline: 1.2237x; 1.2237x over previous
#include <cuda_runtime.h>
#include <cuda_bf16.h>
#include <cstdint>

// Problem constants
#define Hn    128
#define Ln    512
#define Bn    128
#define VOCABn 32000
#define NPTn  1023                 // 2L-1 nodes per tree
#define NTOT  (Bn * NPTn)          // 130944 nodes
#define NLEAF (Bn * Ln)            // 65536 leaves

// Persistent device state (no allocation allowed)
__device__ float g_h[NTOT * Hn];                       // fp32 h (only roots written; final proj)
__device__ float g_c[NTOT * Hn];                       // fp32 c chain
__device__ __nv_bfloat16 g_hb[NTOT * Hn];              // bf16 h mirror (GEMM operand)
__device__ __nv_bfloat16 g_embB[VOCABn * Hn];          // bf16 emb
// Weight layout: gate-grouped per 8-d block: col = (d/8)*G*8 + g*8 + (d%8)
__device__ __nv_bfloat16 g_WTb[640 * 256];             // [Ufw|Uiou]^T fused, G=5
__device__ __nv_bfloat16 g_WioTb[384 * 128];           // W_iou^T, G=3

// HW tanh (single MUFU op, sm_75+); sigmoid via tanh identity.
__device__ __forceinline__ float tanh_ap(float x) {
    float r; asm("tanh.approx.f32 %0, %1;" : "=f"(r) : "f"(x)); return r;
}
__device__ __forceinline__ float sigm_ap(float x) {
    return fmaf(0.5f, tanh_ap(0.5f * x), 0.5f);
}

// m16n8k16 bf16 MMA, fp32 accum (legacy HMMA path — valid on plain compute_103)
__device__ __forceinline__ void mma_bf16(float& c0, float& c1, float& c2, float& c3,
                                         uint32_t a0, uint32_t a1, uint32_t a2, uint32_t a3,
                                         uint32_t b0, uint32_t b1) {
    asm volatile(
        "mma.sync.aligned.m16n8k16.row.col.f32.bf16.bf16.f32 "
        "{%0,%1,%2,%3}, {%4,%5,%6,%7}, {%8,%9}, {%0,%1,%2,%3};"
        : "+f"(c0), "+f"(c1), "+f"(c2), "+f"(c3)
        : "r"(a0), "r"(a1), "r"(a2), "r"(a3), "r"(b0), "r"(b1));
}

__device__ __forceinline__ void ldsm4(uint32_t& r0, uint32_t& r1, uint32_t& r2, uint32_t& r3,
                                      uint32_t addr) {
    asm volatile("ldmatrix.sync.aligned.m8n8.x4.shared.b16 {%0,%1,%2,%3}, [%4];"
                 : "=r"(r0), "=r"(r1), "=r"(r2), "=r"(r3) : "r"(addr));
}
__device__ __forceinline__ void ldsm2(uint32_t& r0, uint32_t& r1, uint32_t addr) {
    asm volatile("ldmatrix.sync.aligned.m8n8.x2.shared.b16 {%0,%1}, [%2];"
                 : "=r"(r0), "=r"(r1) : "r"(addr));
}

__device__ __forceinline__ uint32_t smem_u32(const void* p) {
    uint32_t a;
    asm("{ .reg .u64 t; cvta.to.shared.u64 t, %1; cvt.u32.u64 %0, t; }" : "=r"(a) : "l"(p));
    return a;
}
__device__ __forceinline__ void cpa16(uint32_t s, const void* g) {
    asm volatile("cp.async.cg.shared.global [%0], [%1], 16;" :: "r"(s), "l"(g));
}
#define CP_COMMIT() asm volatile("cp.async.commit_group;" ::: "memory")
#define CP_WAIT(N)  asm volatile("cp.async.wait_group %0;" :: "n"(N) : "memory")

// ---------------------------------------------------------------------------
// Prep kernels. New permutation: for G gates, col c decodes as
//   group = c / (8G), g = (c % (8G)) / 8, d = group*8 + (c % 8)
// Level G=5: g0=Ufw[:,d], g1=Ufw[:,128+d], g2..4=Uiou[:,{0,128,256}+d]
// Leaf  G=3: g=Wiou[:, g*128+d]
// ---------------------------------------------------------------------------
__global__ __launch_bounds__(256) void prep_WT(const float* __restrict__ Ufw,
                                               const float* __restrict__ Uiou) {
    int idx = blockIdx.x * 256 + threadIdx.x;
    if (idx >= 640 * 256) return;
    int c = idx >> 8, k = idx & 255;
    int group = c / 40, jj = c % 40;
    int g = jj >> 3, d = group * 8 + (jj & 7);
    float v;
    if (g == 0)      v = Ufw[k * 256 + d];
    else if (g == 1) v = Ufw[k * 256 + 128 + d];
    else             v = Uiou[k * 384 + (g - 2) * 128 + d];
    g_WTb[idx] = __float2bfloat16(v);
}
__global__ __launch_bounds__(256) void prep_WioT(const float* __restrict__ Wiou) {
    int idx = blockIdx.x * 256 + threadIdx.x;
    if (idx >= 384 * 128) return;
    int c = idx >> 7, k = idx & 127;
    int group = c / 24, jj = c % 24;
    int g = jj >> 3, d = group * 8 + (jj & 7);
    g_WioTb[idx] = __float2bfloat16(Wiou[k * 384 + g * 128 + d]);
}
__global__ __launch_bounds__(256) void prep_emb(const float* __restrict__ emb) {
    int idx = blockIdx.x * 256 + threadIdx.x;           // VOCABn*Hn/2
    float2 v = *(const float2*)(emb + idx * 2);
    __nv_bfloat162 t = __floats2bfloat162_rn(v.x, v.y);
    *(__nv_bfloat162*)(g_embB + idx * 2) = t;
}

// ---------------------------------------------------------------------------
// Fused bf16-MMA GEMM + register-resident LSTM apply.
// cp.async double-buffered 64-K chunks, ldmatrix fragments.
// Gate grouping puts all G gates of a d-pair into one thread's acc fragment:
// n8 tile index nt encodes (gate g [, d-subgroup]); thread (grp,qid) owns
// rows {grp, grp+8} x d {2qid, 2qid+1}. Apply runs from acc regs, writes
// g_c (float2) / g_hb (bf16x2) [+ g_h at root level]. No out smem at all.
// LEAF:  A = g_embB[label[node]] (K=128), NCOLS=96  (4x8 d-groups x 3 gates)
// LEVEL: A = g_hb at child base (K=256),  NCOLS=80  (2x8 d-groups x 5 gates)
// ---------------------------------------------------------------------------
#define SABY 144          // bytes per staged row

template <int CM, int NCOLS, int KTOT, int GATES, int MINB, bool LEAF>
__global__ __launch_bounds__(256, MINB)
void fused_gemm(const int* __restrict__ label,
                const float* __restrict__ b_iou, const float* __restrict__ Ufb,
                int shift, int off, int choff) {
    const int MTT  = CM / 64;            // m16 tiles per warp (4 M-warps)
    const int NTT  = NCOLS / 16;         // n8 tiles per warp  (2 N-warps)
    const int NCH  = KTOT / 64;          // K chunks
    const int BUFB = (CM + NCOLS) * SABY;

    extern __shared__ float dyn[];       // 2 stage buffers
    char* dynb = (char*)dyn;
    __shared__ int abase[CM];

    const __nv_bfloat16* Ab = LEAF ? g_embB : g_hb;
    const __nv_bfloat16* BT = LEAF ? g_WioTb : g_WTb;

    int tid  = threadIdx.x;
    int wid  = tid >> 5, lane = tid & 31;
    int grp  = lane >> 2, qid = lane & 3;
    int row0 = blockIdx.x * CM;
    int col0 = blockIdx.y * NCOLS;
    int wm0  = (wid >> 1) * (CM / 4);
    int wn0  = (wid & 1) * (NCOLS / 2);

    if (tid < CM) {
        int r = row0 + tid;
        int base;
        if (LEAF) {
            int g = (r >> 9) * NPTn + (r & 511);
            base = label[g] * Hn;
        } else {
            int t = r >> shift, j = r & ((1 << shift) - 1);
            base = (t * NPTn + choff + 2 * j) * Hn;
        }
        abase[tid] = base;
    }
    __syncthreads();

    uint32_t sbase = smem_u32(dynb);

    // Per-thread ldmatrix base addresses (buffer 0, chunk 0).
    int arow = (lane & 7) + ((lane >> 3) & 1) * 8;
    uint32_t aaddr0 = sbase + (uint32_t)(wm0 + arow) * SABY + ((lane >> 4) * 16);
    int brow = (lane & 7) + (lane >> 4) * 8;
    uint32_t baddr0 = sbase + (uint32_t)CM * SABY + (uint32_t)(wn0 + brow) * SABY
                    + (((lane >> 3) & 1) * 16);
    uint32_t baddr2 = sbase + (uint32_t)CM * SABY + (uint32_t)(wn0 + (lane & 7)) * SABY
                    + (((lane >> 3) & 1) * 16);

    auto stage = [&](int kk, int buf) {
        uint32_t sb = sbase + buf * BUFB;
#pragma unroll
        for (int e = 0; e < CM / 32; e++) {
            int i = tid + e * 256;
            int m = i >> 3, q = i & 7;
            cpa16(sb + m * SABY + q * 16, Ab + abase[m] + kk + q * 8);
        }
#pragma unroll
        for (int e = 0; e < (NCOLS * 8 + 255) / 256; e++) {
            int i = tid + e * 256;
            if (i < NCOLS * 8) {
                int n = i >> 3, q = i & 7;
                cpa16(sb + CM * SABY + n * SABY + q * 16,
                      BT + (size_t)(col0 + n) * KTOT + kk + q * 8);
            }
        }
    };

    float acc[MTT][NTT][4];
#pragma unroll
    for (int mt = 0; mt < MTT; mt++)
#pragma unroll
        for (int nt = 0; nt < NTT; nt++)
#pragma unroll
            for (int p = 0; p < 4; p++) acc[mt][nt][p] = 0.0f;

    stage(0, 0);
    CP_COMMIT();

    for (int ch = 0; ch < NCH; ch++) {
        if (ch + 1 < NCH) {
            stage((ch + 1) * 64, (ch + 1) & 1);
            CP_COMMIT();
            CP_WAIT(1);
        } else {
            CP_WAIT(0);
        }
        __syncthreads();

        uint32_t bufo = (uint32_t)(ch & 1) * BUFB;
#pragma unroll
        for (int ks = 0; ks < 4; ks++) {             // 4 x k16 = 64
            uint32_t kb = bufo + ks * 32;
            uint32_t a[MTT][4];
#pragma unroll
            for (int mt = 0; mt < MTT; mt++)
                ldsm4(a[mt][0], a[mt][1], a[mt][2], a[mt][3],
                      aaddr0 + kb + mt * 16 * SABY);
            uint32_t b[NTT][2];
#pragma unroll
            for (int np = 0; np < NTT / 2; np++)
                ldsm4(b[2 * np][0], b[2 * np][1], b[2 * np + 1][0], b[2 * np + 1][1],
                      baddr0 + kb + np * 16 * SABY);
            if (NTT & 1)
                ldsm2(b[NTT - 1][0], b[NTT - 1][1],
                      baddr2 + kb + (NTT - 1) * 8 * SABY);
#pragma unroll
            for (int mt = 0; mt < MTT; mt++)
#pragma unroll
                for (int nt = 0; nt < NTT; nt++)
                    mma_bf16(acc[mt][nt][0], acc[mt][nt][1], acc[mt][nt][2], acc[mt][nt][3],
                             a[mt][0], a[mt][1], a[mt][2], a[mt][3],
                             b[nt][0], b[nt][1]);
        }
        __syncthreads();
    }

    // -------- Register-resident apply --------
    // acc[mt][nt][2h+dd] = gate value at (row wm0+mt*16+grp+8h, d = dgE+dd)
    const int NG = NTT / GATES;              // d-subgroups per warp half (1 or 2)
#pragma unroll
    for (int sg = 0; sg < NG; sg++) {
        int dgE = blockIdx.y * (NCOLS >> 3) * 8 / GATES;   // base d of CTA
        dgE = blockIdx.y * ((NCOLS / GATES)) + (wid & 1) * (NCOLS / GATES / 2)
            + sg * 8 + 2 * qid;
        // hoisted per-d-pair biases
        float2 biP = *(const float2*)&b_iou[dgE];
        float2 boP = *(const float2*)&b_iou[128 + dgE];
        float2 buP = *(const float2*)&b_iou[256 + dgE];
        float2 bflP = make_float2(0.f, 0.f), bfrP = make_float2(0.f, 0.f);
        if (!LEAF) {
            bflP = *(const float2*)&Ufb[dgE];
            bfrP = *(const float2*)&Ufb[128 + dgE];
        }
#pragma unroll
        for (int mt = 0; mt < MTT; mt++) {
#pragma unroll
            for (int h = 0; h < 2; h++) {
                int R = row0 + wm0 + mt * 16 + grp + h * 8;
                float cc[2], hh[2];
                if (LEAF) {
                    int node = (R >> 9) * NPTn + (R & 511);
#pragma unroll
                    for (int dd = 0; dd < 2; dd++) {
                        int p = 2 * h + dd;
                        float bi = dd ? biP.y : biP.x;
                        float bo = dd ? boP.y : boP.x;
                        float bu = dd ? buP.y : buP.x;
                        float ci = sigm_ap(acc[mt][sg * 3 + 0][p] + bi)
                                 * tanh_ap(acc[mt][sg * 3 + 2][p] + bu);
                        cc[dd] = ci;
                        hh[dd] = sigm_ap(acc[mt][sg * 3 + 1][p] + bo) * tanh_ap(ci);
                    }
                    *(float2*)&g_c[node * Hn + dgE] = make_float2(cc[0], cc[1]);
                    *(__nv_bfloat162*)&g_hb[node * Hn + dgE] =
                        __floats2bfloat162_rn(hh[0], hh[1]);
                } else {
                    int t = R >> shift, j = R & ((1 << shift) - 1);
                    int tb = t * NPTn;
                    int node = tb + off + j;
                    int left = tb + choff + 2 * j;
                    float2 clP = *(const float2*)&g_c[left * Hn + dgE];
                    float2 crP = *(const float2*)&g_c[(left + 1) * Hn + dgE];
#pragma unroll
                    for (int dd = 0; dd < 2; dd++) {
                        int p = 2 * h + dd;
                        float bi = dd ? biP.y : biP.x;
                        float bo = dd ? boP.y : boP.x;
                        float bu = dd ? buP.y : buP.x;
                        float bfl = dd ? bflP.y : bflP.x;
                        float bfr = dd ? bfrP.y : bfrP.x;
                        float cl = dd ? clP.y : clP.x;
                        float cr = dd ? crP.y : crP.x;
                        float fl = sigm_ap(acc[mt][0][p] + bfl);
                        float fr = sigm_ap(acc[mt][1][p] + bfr);
                        float cred = fl * cl + fr * cr;
                        float ci = sigm_ap(acc[mt][2][p] + bi)
                                 * tanh_ap(acc[mt][4][p] + bu) + cred;
                        cc[dd] = ci;
                        hh[dd] = sigm_ap(acc[mt][3][p] + bo) * tanh_ap(ci);
                    }
                    *(float2*)&g_c[node * Hn + dgE] = make_float2(cc[0], cc[1]);
                    *(__nv_bfloat162*)&g_hb[node * Hn + dgE] =
                        __floats2bfloat162_rn(hh[0], hh[1]);
                    if (shift == 0)
                        *(float2*)&g_h[node * Hn + dgE] = make_float2(hh[0], hh[1]);
                }
            }
        }
    }
}

// Root projection + log_softmax. grid 128 (trees), block 128 (out dims).
__global__ __launch_bounds__(128) void final_kernel(const float* __restrict__ W,
                                                    const float* __restrict__ b,
                                                    float* __restrict__ out) {
    __shared__ float hr[128];
    __shared__ float red[128];
    int t = blockIdx.x, o = threadIdx.x;
    hr[o] = g_h[(t * NPTn + NPTn - 1) * Hn + o];
    __syncthreads();
    float acc = b[o];
#pragma unroll 8
    for (int k = 0; k < 128; k++) acc += hr[k] * W[k * 128 + o];
    red[o] = acc;
    __syncthreads();
#pragma unroll
    for (int s = 64; s > 0; s >>= 1) {
        if (o < s) red[o] = fmaxf(red[o], red[o + s]);
        __syncthreads();
    }
    float mx = red[0];
    __syncthreads();
    red[o] = expf(acc - mx);
    __syncthreads();
#pragma unroll
    for (int s = 64; s > 0; s >>= 1) {
        if (o < s) red[o] += red[o + s];
        __syncthreads();
    }
    out[t * 128 + o] = acc - mx - logf(red[0]);
}

// ---------------------------------------------------------------------------
// Inputs (metadata order): label, emb, W_iou, U_iou, b_iou, U_f_w, U_f_b, W_out, b_out
// ---------------------------------------------------------------------------
#define LEAF_SMEM  (2 * (128 + 96) * SABY)      // 64512
#define LV128_SMEM (2 * (128 + 80) * SABY)      // 59904
#define LV64_SMEM  (2 * (64 + 80) * SABY)       // 41472

extern "C" void kernel_launch(void* const* d_in, const int* in_sizes, int n_in,
                              void* d_out, int out_size) {
    const int*   label = (const int*)  d_in[0];
    const float* emb   = (const float*)d_in[1];
    const float* W_iou = (const float*)d_in[2];
    const float* U_iou = (const float*)d_in[3];
    const float* b_iou = (const float*)d_in[4];
    const float* U_f_w = (const float*)d_in[5];
    const float* U_f_b = (const float*)d_in[6];
    const float* W_out = (const float*)d_in[7];
    const float* b_out = (const float*)d_in[8];
    float* out = (float*)d_out;

    // Opt-in dynamic smem (> 48 KB). Host-side attribute set; capture-safe.
    cudaFuncSetAttribute((const void*)fused_gemm<128, 96, 128, 3, 2, true>,
                         cudaFuncAttributeMaxDynamicSharedMemorySize, LEAF_SMEM);
    cudaFuncSetAttribute((const void*)fused_gemm<128, 80, 256, 5, 3, false>,
                         cudaFuncAttributeMaxDynamicSharedMemorySize, LV128_SMEM);
    cudaFuncSetAttribute((const void*)fused_gemm<64, 80, 256, 5, 3, false>,
                         cudaFuncAttributeMaxDynamicSharedMemorySize, LV64_SMEM);

    prep_WT<<<640, 256>>>(U_f_w, U_iou);
    prep_WioT<<<192, 256>>>(W_iou);
    prep_emb<<<(VOCABn * Hn / 2) / 256, 256>>>(emb);

    // Leaves: fused [65536,128]@[128,384(permuted)] + cell update
    fused_gemm<128, 96, 128, 3, 2, true>
        <<<dim3(NLEAF / 128, 4), 256, LEAF_SMEM>>>(label, b_iou, nullptr, 0, 0, 0);

    for (int shift = 8; shift >= 0; shift--) {
        int cnt   = 1 << shift;                 // 256 .. 1
        int off   = NPTn - (2 * cnt - 1);
        int choff = NPTn - (4 * cnt - 1);
        int nd    = Bn * cnt;                   // 32768 .. 128
        if (nd >= 8192)
            fused_gemm<128, 80, 256, 5, 3, false>
                <<<dim3(nd / 128, 8), 256, LV128_SMEM>>>(label, b_iou, U_f_b,
                                                         shift, off, choff);
        else
            fused_gemm<64, 80, 256, 5, 3, false>
                <<<dim3(nd / 64, 8), 256, LV64_SMEM>>>(label, b_iou, U_f_b,
                                                       shift, off, choff);
    }

    final_kernel<<<Bn, 128>>>(W_out, b_out, out);
}